// round 4
// baseline (speedup 1.0000x reference)
#include <cuda_runtime.h>
#include <cstdint>

#define BATCH 8192
#define IND   128
#define HID   1024
#define OUTD  128
#define NW    8
#define RPW   4
#define RPC   (NW*RPW)     // 32 rows per CTA
#define TW    128          // column tile width
#define NTILE (HID/TW)     // 8
#define SLEN  (IND + HID)  // 1152: [u(128); s(1024)]
#define STGP  128          // stage pitch (floats per j-row)

// smem floats: sh = NW*SLEN*4 float-quads; stg = 2 x (32*128)
#define SH_FLOATS (NW*SLEN*4)
#define SMEM_FLOATS (SH_FLOATS + 2*32*STGP)
#define SMEM_BYTES  (SMEM_FLOATS * 4)

typedef unsigned long long ull;

__device__ __forceinline__ ull ffma2(ull a, ull b, ull c) {
    ull d; asm("fma.rn.f32x2 %0, %1, %2, %3;" : "=l"(d) : "l"(a), "l"(b), "l"(c));
    return d;
}
__device__ __forceinline__ ull dup2(float x) {
    ull d; asm("mov.b64 %0, {%1, %1};" : "=l"(d) : "f"(x)); return d;
}
__device__ __forceinline__ ull pack2(float x, float y) {
    ull d; asm("mov.b64 %0, {%1, %2};" : "=l"(d) : "f"(x), "f"(y)); return d;
}
__device__ __forceinline__ float2 unpack2(ull v) {
    float2 f; asm("mov.b64 {%0, %1}, %2;" : "=f"(f.x), "=f"(f.y) : "l"(v)); return f;
}
__device__ __forceinline__ float fast_tanh(float x) {
    // tanh(x) = 1 - 2/(exp(2x)+1), ex2.approx + rcp.approx (~1e-7 abs err)
    float e; asm("ex2.approx.f32 %0, %1;" : "=f"(e) : "f"(x * 2.8853900817779268f));
    float r; asm("rcp.approx.f32 %0, %1;" : "=f"(r) : "f"(e + 1.0f));
    return fmaf(-2.0f, r, 1.0f);
}

// stage a 32j x 128c chunk, transposed: buf[j*STGP + c] = src[c*ld + j]
__device__ __forceinline__ void stage_chunk(float* buf, const float* __restrict__ src,
                                            int ld, int tid) {
    const int c    = tid >> 1;
    const int part = tid & 1;            // 16 floats each
    const float4* s4 = (const float4*)(src + (size_t)c * ld + part * 16);
    #pragma unroll
    for (int i = 0; i < 4; ++i) {
        float4 v = s4[i];
        int j = part * 16 + i * 4;
        buf[(j+0)*STGP + c] = v.x;
        buf[(j+1)*STGP + c] = v.y;
        buf[(j+2)*STGP + c] = v.z;
        buf[(j+3)*STGP + c] = v.w;
    }
}

// dense 32-j update: acc[cols lane*4..+3] += s_j * b[j][col]
__device__ __forceinline__ void dense32(ull a01[4], ull a23[4],
                                        const ulonglong2* __restrict__ sbase,
                                        const float4* __restrict__ bbuf,
                                        int lane, bool active) {
    if (!active) return;
    #pragma unroll 8
    for (int j = 0; j < 32; ++j) {
        ulonglong2 sv = sbase[j];            // uniform broadcast: (r0,r1),(r2,r3)
        float4 b = bbuf[j*32 + lane];        // 4 cols for this lane
        ull b0 = dup2(b.x), b1 = dup2(b.y), b2 = dup2(b.z), b3 = dup2(b.w);
        a01[0] = ffma2(sv.x, b0, a01[0]);  a23[0] = ffma2(sv.y, b0, a23[0]);
        a01[1] = ffma2(sv.x, b1, a01[1]);  a23[1] = ffma2(sv.y, b1, a23[1]);
        a01[2] = ffma2(sv.x, b2, a01[2]);  a23[2] = ffma2(sv.y, b2, a23[2]);
        a01[3] = ffma2(sv.x, b3, a01[3]);  a23[3] = ffma2(sv.y, b3, a23[3]);
    }
}

// sequential 32-step sweep for diag sub-chunk cj (cols 32cj..32cj+31, lanes 8cj..8cj+7)
__device__ __forceinline__ void sweep32(ull a01[4], ull a23[4],
                                        const float4* __restrict__ bbuf,
                                        float4* __restrict__ sdst,
                                        int lane, int cj) {
    const int lbase = cj * 8;
    const int lloc  = lane - lbase;
    const bool act  = (lloc >= 0) && (lloc < 8);
    const int cl    = lloc * 4;          // local col base (garbage if !act)
    #pragma unroll
    for (int i = 0; i < 32; ++i) {
        const int q = i & 3;
        const int owner = lbase + (i >> 2);
        float2 p01 = unpack2(a01[q]);
        float2 p23 = unpack2(a23[q]);
        float t0 = fast_tanh(p01.x), t1 = fast_tanh(p01.y);
        float t2 = fast_tanh(p23.x), t3 = fast_tanh(p23.y);
        float v0 = __shfl_sync(0xffffffffu, t0, owner);
        float v1 = __shfl_sync(0xffffffffu, t1, owner);
        float v2 = __shfl_sync(0xffffffffu, t2, owner);
        float v3 = __shfl_sync(0xffffffffu, t3, owner);
        ull s01 = pack2(v0, v1);
        ull s23 = pack2(v2, v3);
        float4 b = bbuf[i*32 + lane];
        if (act) {
            if (cl + 0 > i) { ull bb = dup2(b.x); a01[0]=ffma2(s01,bb,a01[0]); a23[0]=ffma2(s23,bb,a23[0]); }
            if (cl + 1 > i) { ull bb = dup2(b.y); a01[1]=ffma2(s01,bb,a01[1]); a23[1]=ffma2(s23,bb,a23[1]); }
            if (cl + 2 > i) { ull bb = dup2(b.z); a01[2]=ffma2(s01,bb,a01[2]); a23[2]=ffma2(s23,bb,a23[2]); }
            if (cl + 3 > i) { ull bb = dup2(b.w); a01[3]=ffma2(s01,bb,a01[3]); a23[3]=ffma2(s23,bb,a23[3]); }
            if (lane == owner) sdst[i] = make_float4(t0, t1, t2, t3);
        }
    }
}

__global__ void __launch_bounds__(256, 1)
ren_kernel(const float* __restrict__ u,  const float* __restrict__ Bw,
           const float* __restrict__ Bs, const float* __restrict__ Ds,
           const float* __restrict__ Dw, float* __restrict__ out)
{
    extern __shared__ float smem[];
    float4* sh  = (float4*)smem;             // [NW][SLEN] float4 (4 batch rows)
    float*  stg = smem + SH_FLOATS;          // 2 x 4096 floats

    const int tid  = threadIdx.x;
    const int warp = tid >> 5;
    const int lane = tid & 31;
    const int r0   = blockIdx.x * RPC + warp * RPW;

    float4* mysh = sh + warp * SLEN;
    // prepend u rows: mysh[0..127] = u (4 rows interleaved)
    for (int k = lane; k < IND; k += 32)
        mysh[k] = make_float4(u[(size_t)(r0+0)*IND + k], u[(size_t)(r0+1)*IND + k],
                              u[(size_t)(r0+2)*IND + k], u[(size_t)(r0+3)*IND + k]);

    // ===== recurrence: 8 column-tiles of width 128 =====
    for (int t = 0; t < NTILE; ++t) {
        const int h0  = t * TW;
        const int nch = 8 + 4*t;     // 4 u-chunks + 4t history + 4 diag
        ull a01[4] = {0,0,0,0}, a23[4] = {0,0,0,0};

        stage_chunk(stg, Bw + (size_t)h0 * IND, IND, tid);  // chunk m=0
        __syncthreads();

        for (int m = 0; m < nch; ++m) {
            float* cur = stg + (m & 1) * (32*STGP);
            if (m + 1 < nch) {
                const int mm = m + 1;
                const float* src = (mm < 4) ? (Bw + (size_t)h0 * IND  + mm * 32)
                                            : (Bs + (size_t)h0 * HID + (size_t)(mm-4) * 32);
                stage_chunk(stg + ((m+1) & 1) * (32*STGP), src, (mm < 4) ? IND : HID, tid);
            }
            const ulonglong2* sbase = (const ulonglong2*)(mysh + 32 * m);  // jbase = 32m
            if (m < 4 + 4*t) {
                dense32(a01, a23, sbase, (const float4*)cur, lane, true);
            } else {
                const int cj = m - 4 - 4*t;
                sweep32(a01, a23, (const float4*)cur, mysh + IND + h0 + 32*cj, lane, cj);
                __syncwarp();
                dense32(a01, a23, sbase, (const float4*)cur, lane, lane >= 8*(cj+1));
            }
            __syncthreads();
        }
    }

    // ===== output: y = [u;s] @ [Dw|Ds]^T, 36 k-chunks =====
    {
        ull a01[4] = {0,0,0,0}, a23[4] = {0,0,0,0};
        stage_chunk(stg, Dw, IND, tid);
        __syncthreads();
        for (int m = 0; m < 36; ++m) {
            float* cur = stg + (m & 1) * (32*STGP);
            if (m + 1 < 36) {
                const int mm = m + 1;
                const float* src = (mm < 4) ? (Dw + mm * 32) : (Ds + (size_t)(mm-4) * 32);
                stage_chunk(stg + ((m+1) & 1) * (32*STGP), src, (mm < 4) ? IND : HID, tid);
            }
            dense32(a01, a23, (const ulonglong2*)(mysh + 32*m), (const float4*)cur, lane, true);
            __syncthreads();
        }

        float2 x01[4], x23[4];
        #pragma unroll
        for (int q = 0; q < 4; ++q) { x01[q] = unpack2(a01[q]); x23[q] = unpack2(a23[q]); }
        float4 v0 = make_float4(x01[0].x, x01[1].x, x01[2].x, x01[3].x);
        float4 v1 = make_float4(x01[0].y, x01[1].y, x01[2].y, x01[3].y);
        float4 v2 = make_float4(x23[0].x, x23[1].x, x23[2].x, x23[3].x);
        float4 v3 = make_float4(x23[0].y, x23[1].y, x23[2].y, x23[3].y);
        ((float4*)(out + (size_t)(r0+0)*OUTD))[lane] = v0;
        ((float4*)(out + (size_t)(r0+1)*OUTD))[lane] = v1;
        ((float4*)(out + (size_t)(r0+2)*OUTD))[lane] = v2;
        ((float4*)(out + (size_t)(r0+3)*OUTD))[lane] = v3;
    }
}

extern "C" void kernel_launch(void* const* d_in, const int* in_sizes, int n_in,
                              void* d_out, int out_size)
{
    const float* u  = (const float*)d_in[0];  // [8192,128]
    const float* Bw = (const float*)d_in[1];  // [1024,128]
    const float* Bs = (const float*)d_in[2];  // [1024,1024]
    const float* Ds = (const float*)d_in[3];  // [128,1024]
    const float* Dw = (const float*)d_in[4];  // [128,128]

    cudaFuncSetAttribute(ren_kernel,
                         cudaFuncAttributeMaxDynamicSharedMemorySize, SMEM_BYTES);
    ren_kernel<<<BATCH / RPC, 256, SMEM_BYTES>>>(u, Bw, Bs, Ds, Dw, (float*)d_out);
}

// round 6
// speedup vs baseline: 2.1870x; 2.1870x over previous
#include <cuda_runtime.h>
#include <cuda_bf16.h>
#include <cstdint>

#define BATCH 8192
#define IND   128
#define HID   1024
#define OUTD  128
#define SK    1152           // S cols: [u(128) | s(1024)]
#define MB    64             // batch rows per CTA -> 128 CTAs
#define THREADS 512
#define NSEG  9

// ---- smem layout (bytes) ----
// two staging sets (A_hi, A_lo: 64x144B; B_hi, B_lo: 128x144B)
#define A_HI 0
#define A_LO 9216
#define B_HI 18432
#define B_LO 36864
#define SET_BYTES 55296      // sets at 0 and 55296
// after MMA of a segment: trans (reuses set0), diag (reuses set1+)
#define TRANS_OFF 0
#define TP 73                // trans pitch (floats)
#define DIAG_OFF 55296
#define DP 132               // diag pitch (floats)
#define SMEM_TOTAL 122880

typedef unsigned long long ull;

// ---- global scratch (hi/lo bf16 split) ----
__device__ __align__(256) __nv_bfloat16 g_S_hi[(size_t)BATCH * SK];
__device__ __align__(256) __nv_bfloat16 g_S_lo[(size_t)BATCH * SK];
__device__ __align__(256) __nv_bfloat16 g_W_hi[(size_t)HID * SK];
__device__ __align__(256) __nv_bfloat16 g_W_lo[(size_t)HID * SK];
__device__ __align__(256) __nv_bfloat16 g_WO_hi[(size_t)OUTD * SK];
__device__ __align__(256) __nv_bfloat16 g_WO_lo[(size_t)OUTD * SK];

__device__ __forceinline__ uint32_t smem_u32(const void* p) {
    uint32_t a;
    asm("{ .reg .u64 t; cvta.to.shared.u64 t, %1; cvt.u32.u64 %0, t; }" : "=r"(a) : "l"(p));
    return a;
}
__device__ __forceinline__ ull ffma2(ull a, ull b, ull c) {
    ull d; asm("fma.rn.f32x2 %0, %1, %2, %3;" : "=l"(d) : "l"(a), "l"(b), "l"(c)); return d;
}
__device__ __forceinline__ ull dup2(float x) {
    ull d; asm("mov.b64 %0, {%1, %1};" : "=l"(d) : "f"(x)); return d;
}
__device__ __forceinline__ ull pack2(float x, float y) {
    ull d; asm("mov.b64 %0, {%1, %2};" : "=l"(d) : "f"(x), "f"(y)); return d;
}
__device__ __forceinline__ float2 unpack2(ull v) {
    float2 f; asm("mov.b64 {%0, %1}, %2;" : "=f"(f.x), "=f"(f.y) : "l"(v)); return f;
}
__device__ __forceinline__ float fast_tanh(float x) {
    // tanh(x) = 1 - 2/(exp(2x)+1), ex2.approx + rcp.approx (~1e-7 abs err)
    float e; asm("ex2.approx.f32 %0, %1;" : "=f"(e) : "f"(x * 2.8853900817779268f));
    float r; asm("rcp.approx.f32 %0, %1;" : "=f"(r) : "f"(e + 1.0f));
    return fmaf(-2.0f, r, 1.0f);
}
__device__ __forceinline__ void ldmx4(uint32_t r[4], uint32_t a) {
    asm volatile("ldmatrix.sync.aligned.m8n8.x4.shared.b16 {%0,%1,%2,%3}, [%4];"
        : "=r"(r[0]), "=r"(r[1]), "=r"(r[2]), "=r"(r[3]) : "r"(a));
}
__device__ __forceinline__ void mma16816(float c[4], const uint32_t a[4],
                                         uint32_t b0, uint32_t b1) {
    asm volatile("mma.sync.aligned.m16n8k16.row.col.f32.bf16.bf16.f32 "
        "{%0,%1,%2,%3}, {%4,%5,%6,%7}, {%8,%9}, {%0,%1,%2,%3};"
        : "+f"(c[0]), "+f"(c[1]), "+f"(c[2]), "+f"(c[3])
        : "r"(a[0]), "r"(a[1]), "r"(a[2]), "r"(a[3]), "r"(b0), "r"(b1));
}

// ======== prologue: split inputs into bf16 hi+lo ========
#define T1 (BATCH * IND)
#define T2 (HID * SK)
#define T3 (OUTD * SK)

__device__ __forceinline__ void store_split(__nv_bfloat16* hi, __nv_bfloat16* lo,
                                            size_t idx, float v) {
    __nv_bfloat16 h = __float2bfloat16_rn(v);
    hi[idx] = h;
    lo[idx] = __float2bfloat16_rn(v - __bfloat162float(h));
}

__global__ void split_kernel(const float* __restrict__ u,  const float* __restrict__ Bw,
                             const float* __restrict__ Bs, const float* __restrict__ Ds,
                             const float* __restrict__ Dw) {
    int idx = blockIdx.x * blockDim.x + threadIdx.x;
    if (idx < T1) {
        int r = idx >> 7, k = idx & 127;
        store_split(g_S_hi, g_S_lo, (size_t)r * SK + k, u[idx]);
    } else if (idx < T1 + T2) {
        int i = idx - T1;
        int n = i / SK, k = i % SK;
        float v = (k < IND) ? Bw[n * IND + k] : Bs[(size_t)n * HID + (k - IND)];
        store_split(g_W_hi, g_W_lo, i, v);
    } else if (idx < T1 + T2 + T3) {
        int i = idx - T1 - T2;
        int n = i / SK, k = i % SK;
        float v = (k < IND) ? Dw[n * IND + k] : Ds[(size_t)n * HID + (k - IND)];
        store_split(g_WO_hi, g_WO_lo, i, v);
    }
}

// stage one K=64 chunk: A (64 rows) + B (128 rows), hi+lo, pitch 144B
__device__ __forceinline__ void stage_set(char* setp,
        const __nv_bfloat16* __restrict__ Sh, const __nv_bfloat16* __restrict__ Sl,
        const __nv_bfloat16* __restrict__ Wh, const __nv_bfloat16* __restrict__ Wl,
        int kg, int tid)
{
    {   // A: 64 rows x 64 bf16 (each thread one 16B piece per buf)
        const int r  = tid >> 3;
        const int ko = (tid & 7) << 3;
        const size_t so = (size_t)r * SK + kg + ko;
        const int d = r * 144 + ko * 2;
        *(uint4*)(setp + A_HI + d) = *(const uint4*)(Sh + so);
        *(uint4*)(setp + A_LO + d) = *(const uint4*)(Sl + so);
    }
    {   // B: 128 rows x 64 bf16 (each thread two 16B pieces per buf)
        const int r  = tid >> 2;
        const int ko = (tid & 3) << 4;
        const size_t so = (size_t)r * SK + kg + ko;
        const int d = r * 144 + ko * 2;
        *(uint4*)(setp + B_HI + d)      = *(const uint4*)(Wh + so);
        *(uint4*)(setp + B_HI + d + 16) = *(const uint4*)(Wh + so + 8);
        *(uint4*)(setp + B_LO + d)      = *(const uint4*)(Wl + so);
        *(uint4*)(setp + B_LO + d + 16) = *(const uint4*)(Wl + so + 8);
    }
}

// ======== main fused kernel ========
__global__ void __launch_bounds__(THREADS, 1)
ren_main(const float* __restrict__ Bs, float* __restrict__ out)
{
    extern __shared__ char smem[];
    const uint32_t sb = smem_u32(smem);
    float* trans = (float*)(smem + TRANS_OFF);
    float* diagf = (float*)(smem + DIAG_OFF);

    const int tid  = threadIdx.x;
    const int wid  = tid >> 5;
    const int lane = tid & 31;
    const int wr   = wid & 1;        // row tile (32 rows)
    const int wc   = wid >> 1;       // col tile (16 cols)
    const int row0 = blockIdx.x * MB;

    const __nv_bfloat16* Sh = g_S_hi + (size_t)row0 * SK;
    const __nv_bfloat16* Sl = g_S_lo + (size_t)row0 * SK;

    const uint32_t rowOff = (uint32_t)(lane & 15) * 144 + (lane & 16);
    const int r_in = lane >> 2;
    const int cp   = (lane & 3) << 1;

    for (int seg = 0; seg < NSEG; ++seg) {
        const bool isOut = (seg == 8);
        const int  h0 = seg * 128;
        const int  NC = isOut ? (SK / 64) : (2 + 2 * seg);
        const __nv_bfloat16* Wh = isOut ? g_WO_hi : (g_W_hi + (size_t)h0 * SK);
        const __nv_bfloat16* Wl = isOut ? g_WO_lo : (g_W_lo + (size_t)h0 * SK);

        float acc[2][2][4];
        #pragma unroll
        for (int a = 0; a < 2; ++a)
            #pragma unroll
            for (int b = 0; b < 2; ++b)
                #pragma unroll
                for (int c = 0; c < 4; ++c) acc[a][b][c] = 0.f;

        stage_set(smem, Sh, Sl, Wh, Wl, 0, tid);
        __syncthreads();

        for (int c = 0; c < NC; ++c) {
            if (c + 1 < NC)
                stage_set(smem + ((c + 1) & 1) * SET_BYTES, Sh, Sl, Wh, Wl, (c + 1) * 64, tid);

            const uint32_t sbase = sb + (c & 1) * SET_BYTES;
            const uint32_t aH = sbase + A_HI + (uint32_t)(32 * wr) * 144 + rowOff;
            const uint32_t aL = sbase + A_LO + (uint32_t)(32 * wr) * 144 + rowOff;
            const uint32_t bH = sbase + B_HI + (uint32_t)(16 * wc) * 144 + rowOff;
            const uint32_t bL = sbase + B_LO + (uint32_t)(16 * wc) * 144 + rowOff;

            #pragma unroll
            for (int ks = 0; ks < 4; ++ks) {
                uint32_t Ah0[4], Ah1[4], Al0[4], Al1[4], Bh[4], Bl[4];
                ldmx4(Ah0, aH + ks * 32);
                ldmx4(Ah1, aH + 16 * 144 + ks * 32);
                ldmx4(Al0, aL + ks * 32);
                ldmx4(Al1, aL + 16 * 144 + ks * 32);
                ldmx4(Bh,  bH + ks * 32);
                ldmx4(Bl,  bL + ks * 32);
                // product hi*hi
                mma16816(acc[0][0], Ah0, Bh[0], Bh[2]);
                mma16816(acc[0][1], Ah0, Bh[1], Bh[3]);
                mma16816(acc[1][0], Ah1, Bh[0], Bh[2]);
                mma16816(acc[1][1], Ah1, Bh[1], Bh[3]);
                // product hi*lo
                mma16816(acc[0][0], Ah0, Bl[0], Bl[2]);
                mma16816(acc[0][1], Ah0, Bl[1], Bl[3]);
                mma16816(acc[1][0], Ah1, Bl[0], Bl[2]);
                mma16816(acc[1][1], Ah1, Bl[1], Bl[3]);
                // product lo*hi
                mma16816(acc[0][0], Al0, Bh[0], Bh[2]);
                mma16816(acc[0][1], Al0, Bh[1], Bh[3]);
                mma16816(acc[1][0], Al1, Bh[0], Bh[2]);
                mma16816(acc[1][1], Al1, Bh[1], Bh[3]);
            }
            __syncthreads();
        }

        if (isOut) {
            #pragma unroll
            for (int mi = 0; mi < 2; ++mi)
                #pragma unroll
                for (int nf = 0; nf < 2; ++nf) {
                    const int row = 32 * wr + 16 * mi + r_in;
                    const int col = 16 * wc + 8 * nf + cp;
                    *(float2*)(out + (size_t)(row0 + row) * OUTD + col) =
                        make_float2(acc[mi][nf][0], acc[mi][nf][1]);
                    *(float2*)(out + (size_t)(row0 + row + 8) * OUTD + col) =
                        make_float2(acc[mi][nf][2], acc[mi][nf][3]);
                }
        } else {
            // ---- transpose acc into smem: trans[col*TP + row]
            #pragma unroll
            for (int mi = 0; mi < 2; ++mi)
                #pragma unroll
                for (int nf = 0; nf < 2; ++nf) {
                    const int rowb = 32 * wr + 16 * mi + r_in;
                    const int colb = 16 * wc + 8 * nf + cp;
                    trans[(colb    ) * TP + rowb    ] = acc[mi][nf][0];
                    trans[(colb + 1) * TP + rowb    ] = acc[mi][nf][1];
                    trans[(colb    ) * TP + rowb + 8] = acc[mi][nf][2];
                    trans[(colb + 1) * TP + rowb + 8] = acc[mi][nf][3];
                }
            __syncthreads();

            // ---- stage diag fp32: diagf[i*DP + c] = Bs[h0+c][h0+i]
            {
                const int c  = tid >> 2;
                const int i0 = (tid & 3) << 5;
                const float4* sp = (const float4*)(Bs + (size_t)(h0 + c) * HID + h0 + i0);
                #pragma unroll
                for (int k = 0; k < 8; ++k) {
                    float4 v = sp[k];
                    const int i = i0 + 4 * k;
                    diagf[(i + 0) * DP + c] = v.x;
                    diagf[(i + 1) * DP + c] = v.y;
                    diagf[(i + 2) * DP + c] = v.z;
                    diagf[(i + 3) * DP + c] = v.w;
                }
            }
            // ---- load sweep acc: warp owns rows 4wid..+3; lane owns cols 4lane..+3
            ull a2[4][2];
            #pragma unroll
            for (int q = 0; q < 4; ++q) {
                const float* tp = trans + (4 * lane + q) * TP + 4 * wid;
                a2[q][0] = pack2(tp[0], tp[1]);
                a2[q][1] = pack2(tp[2], tp[3]);
            }
            __syncthreads();

            // ---- 128-step sequential sweep (shfl-only exchange)
            const int grow = row0 + 4 * wid + (lane & 3);
            __nv_bfloat16* ghi = g_S_hi + (size_t)grow * SK + IND + h0;
            __nv_bfloat16* glo = g_S_lo + (size_t)grow * SK + IND + h0;
            const int cbase = 4 * lane;

            #pragma unroll 4
            for (int ib = 0; ib < 32; ++ib) {
                #pragma unroll
                for (int q = 0; q < 4; ++q) {
                    const int i = 4 * ib + q;
                    ull g0 = __shfl_sync(0xffffffffu, a2[q][0], ib);
                    ull g1 = __shfl_sync(0xffffffffu, a2[q][1], ib);
                    float2 pp = unpack2((lane & 2) ? g1 : g0);
                    float v = (lane & 1) ? pp.y : pp.x;
                    float t = fast_tanh(v);
                    if (lane < 4) {
                        __nv_bfloat16 hb = __float2bfloat16_rn(t);
                        ghi[i] = hb;
                        glo[i] = __float2bfloat16_rn(t - __bfloat162float(hb));
                    }
                    float t0 = __shfl_sync(0xffffffffu, t, 0);
                    float t1 = __shfl_sync(0xffffffffu, t, 1);
                    float t2 = __shfl_sync(0xffffffffu, t, 2);
                    float t3 = __shfl_sync(0xffffffffu, t, 3);
                    ull s01 = pack2(t0, t1), s23 = pack2(t2, t3);
                    float4 b = *(const float4*)(diagf + i * DP + cbase);
                    if (cbase + 0 > i) { ull bb = dup2(b.x);
                        a2[0][0] = ffma2(s01, bb, a2[0][0]); a2[0][1] = ffma2(s23, bb, a2[0][1]); }
                    if (cbase + 1 > i) { ull bb = dup2(b.y);
                        a2[1][0] = ffma2(s01, bb, a2[1][0]); a2[1][1] = ffma2(s23, bb, a2[1][1]); }
                    if (cbase + 2 > i) { ull bb = dup2(b.z);
                        a2[2][0] = ffma2(s01, bb, a2[2][0]); a2[2][1] = ffma2(s23, bb, a2[2][1]); }
                    if (cbase + 3 > i) { ull bb = dup2(b.w);
                        a2[3][0] = ffma2(s01, bb, a2[3][0]); a2[3][1] = ffma2(s23, bb, a2[3][1]); }
                }
            }
            __syncthreads();
        }
    }
}

extern "C" void kernel_launch(void* const* d_in, const int* in_sizes, int n_in,
                              void* d_out, int out_size)
{
    const float* u  = (const float*)d_in[0];  // [8192,128]
    const float* Bw = (const float*)d_in[1];  // [1024,128]
    const float* Bs = (const float*)d_in[2];  // [1024,1024]
    const float* Ds = (const float*)d_in[3];  // [128,1024]
    const float* Dw = (const float*)d_in[4];  // [128,128]

    const int NTOT = T1 + T2 + T3;
    split_kernel<<<(NTOT + 255) / 256, 256>>>(u, Bw, Bs, Ds, Dw);

    cudaFuncSetAttribute(ren_main, cudaFuncAttributeMaxDynamicSharedMemorySize, SMEM_TOTAL);
    ren_main<<<BATCH / MB, THREADS, SMEM_TOTAL>>>(Bs, (float*)d_out);
}

// round 7
// speedup vs baseline: 2.3589x; 1.0786x over previous
#include <cuda_runtime.h>
#include <cuda_bf16.h>
#include <cstdint>

#define BATCH 8192
#define IND   128
#define HID   1024
#define OUTD  128
#define SK    1152           // S cols: [u(128) | s(1024)]
#define MB    64             // batch rows per CTA -> 128 CTAs
#define THREADS 512
#define NSEG  9

// per-chunk buffer (24576 B): A 64x64B hi/lo, B 128x64B hi/lo (swizzled)
#define CH_A_HI 0
#define CH_A_LO 4096
#define CH_B_HI 8192
#define CH_B_LO 16384
#define CH_BYTES 24576
// group g owns 2 buffers at g*49152 + b*24576; trans_g overlays them after MMA
#define GRP_BYTES 49152
#define TP 73                // trans pitch (floats)
#define DIAG_OFF 98304
#define DP 132               // diag pitch (floats)
#define SMEM_TOTAL (98304 + 128*DP*4)   // 165888

typedef unsigned long long ull;

__device__ __align__(256) __nv_bfloat16 g_S_hi[(size_t)BATCH * SK];
__device__ __align__(256) __nv_bfloat16 g_S_lo[(size_t)BATCH * SK];
__device__ __align__(256) __nv_bfloat16 g_W_hi[(size_t)HID * SK];
__device__ __align__(256) __nv_bfloat16 g_W_lo[(size_t)HID * SK];
__device__ __align__(256) __nv_bfloat16 g_WO_hi[(size_t)OUTD * SK];
__device__ __align__(256) __nv_bfloat16 g_WO_lo[(size_t)OUTD * SK];

__device__ __forceinline__ uint32_t smem_u32(const void* p) {
    uint32_t a;
    asm("{ .reg .u64 t; cvta.to.shared.u64 t, %1; cvt.u32.u64 %0, t; }" : "=r"(a) : "l"(p));
    return a;
}
__device__ __forceinline__ ull ffma2(ull a, ull b, ull c) {
    ull d; asm("fma.rn.f32x2 %0, %1, %2, %3;" : "=l"(d) : "l"(a), "l"(b), "l"(c)); return d;
}
__device__ __forceinline__ ull dup2(float x) {
    ull d; asm("mov.b64 %0, {%1, %1};" : "=l"(d) : "f"(x)); return d;
}
__device__ __forceinline__ ull pack2(float x, float y) {
    ull d; asm("mov.b64 %0, {%1, %2};" : "=l"(d) : "f"(x), "f"(y)); return d;
}
__device__ __forceinline__ float2 unpack2(ull v) {
    float2 f; asm("mov.b64 {%0, %1}, %2;" : "=f"(f.x), "=f"(f.y) : "l"(v)); return f;
}
__device__ __forceinline__ float fast_tanh(float x) {
    float e; asm("ex2.approx.f32 %0, %1;" : "=f"(e) : "f"(x * 2.8853900817779268f));
    float r; asm("rcp.approx.f32 %0, %1;" : "=f"(r) : "f"(e + 1.0f));
    return fmaf(-2.0f, r, 1.0f);
}
__device__ __forceinline__ void ldmx4(uint32_t r[4], uint32_t a) {
    asm volatile("ldmatrix.sync.aligned.m8n8.x4.shared.b16 {%0,%1,%2,%3}, [%4];"
        : "=r"(r[0]), "=r"(r[1]), "=r"(r[2]), "=r"(r[3]) : "r"(a));
}
__device__ __forceinline__ void mma16816(float c[4], const uint32_t a[4],
                                         uint32_t b0, uint32_t b1) {
    asm volatile("mma.sync.aligned.m16n8k16.row.col.f32.bf16.bf16.f32 "
        "{%0,%1,%2,%3}, {%4,%5,%6,%7}, {%8,%9}, {%0,%1,%2,%3};"
        : "+f"(c[0]), "+f"(c[1]), "+f"(c[2]), "+f"(c[3])
        : "r"(a[0]), "r"(a[1]), "r"(a[2]), "r"(a[3]), "r"(b0), "r"(b1));
}
__device__ __forceinline__ void cp16(uint32_t dst, const void* src) {
    asm volatile("cp.async.cg.shared.global [%0], [%1], 16;" :: "r"(dst), "l"(src));
}
#define CP_COMMIT() asm volatile("cp.async.commit_group;" ::: "memory")
#define CP_WAIT(n)  asm volatile("cp.async.wait_group %0;" :: "n"(n) : "memory")
#define BAR_G(id)   asm volatile("bar.sync %0, 256;" :: "r"(id) : "memory")

// ======== prologue: split inputs into bf16 hi+lo ========
#define T1 (BATCH * IND)
#define T2 (HID * SK)
#define T3 (OUTD * SK)

__device__ __forceinline__ void store_split(__nv_bfloat16* hi, __nv_bfloat16* lo,
                                            size_t idx, float v) {
    __nv_bfloat16 h = __float2bfloat16_rn(v);
    hi[idx] = h;
    lo[idx] = __float2bfloat16_rn(v - __bfloat162float(h));
}

__global__ void split_kernel(const float* __restrict__ u,  const float* __restrict__ Bw,
                             const float* __restrict__ Bs, const float* __restrict__ Ds,
                             const float* __restrict__ Dw) {
    int idx = blockIdx.x * blockDim.x + threadIdx.x;
    if (idx < T1) {
        int r = idx >> 7, k = idx & 127;
        store_split(g_S_hi, g_S_lo, (size_t)r * SK + k, u[idx]);
    } else if (idx < T1 + T2) {
        int i = idx - T1;
        int n = i / SK, k = i % SK;
        float v = (k < IND) ? Bw[n * IND + k] : Bs[(size_t)n * HID + (k - IND)];
        store_split(g_W_hi, g_W_lo, i, v);
    } else if (idx < T1 + T2 + T3) {
        int i = idx - T1 - T2;
        int n = i / SK, k = i % SK;
        float v = (k < IND) ? Dw[n * IND + k] : Ds[(size_t)n * HID + (k - IND)];
        store_split(g_WO_hi, g_WO_lo, i, v);
    }
}

// stage one K=32 chunk (A 64 rows, B 128 rows, hi+lo) with cp.async, swizzled
__device__ __forceinline__ void stage_chunk(uint32_t bufb,
        const __nv_bfloat16* __restrict__ Sh, const __nv_bfloat16* __restrict__ Sl,
        const __nv_bfloat16* __restrict__ Wh, const __nv_bfloat16* __restrict__ Wl,
        int kcol, int gt)
{
    {   // A: 256 pieces per buf -> 1/thread each
        const int row = gt >> 2, c16 = gt & 3;
        const uint32_t d = (uint32_t)row * 64 + 16u * (uint32_t)(c16 ^ ((row >> 1) & 3));
        const size_t so = (size_t)row * SK + kcol + c16 * 8;
        cp16(bufb + CH_A_HI + d, Sh + so);
        cp16(bufb + CH_A_LO + d, Sl + so);
    }
    #pragma unroll
    for (int h = 0; h < 2; ++h) {   // B: 512 pieces per buf -> 2/thread each
        const int p = gt + h * 256;
        const int row = p >> 2, c16 = p & 3;
        const uint32_t d = (uint32_t)row * 64 + 16u * (uint32_t)(c16 ^ ((row >> 1) & 3));
        const size_t so = (size_t)row * SK + kcol + c16 * 8;
        cp16(bufb + CH_B_HI + d, Wh + so);
        cp16(bufb + CH_B_LO + d, Wl + so);
    }
}

// ======== main fused kernel ========
__global__ void __launch_bounds__(THREADS, 1)
ren_main(const float* __restrict__ Bs, float* __restrict__ out)
{
    extern __shared__ char smem[];
    const uint32_t sb = smem_u32(smem);
    float* diagf = (float*)(smem + DIAG_OFF);

    const int tid  = threadIdx.x;
    const int wid  = tid >> 5;
    const int lane = tid & 31;
    const int g    = wid >> 3;       // warp group (K-split)
    const int gt   = tid & 255;      // thread id within group
    const int w8   = wid & 7;        // warp id within group
    const int wr   = w8 & 1;         // 32-row strip
    const int wc   = w8 >> 1;        // 32-col strip
    const int row0 = blockIdx.x * MB;

    const __nv_bfloat16* Sh = g_S_hi + (size_t)row0 * SK;
    const __nv_bfloat16* Sl = g_S_lo + (size_t)row0 * SK;

    // ldmatrix lane addressing (swizzled 64B rows)
    const int l15  = lane & 15;
    const uint32_t rowA = (uint32_t)(32 * wr + l15) * 64;
    const uint32_t rowB = (uint32_t)(32 * wc + l15) * 64;
    const int swzr  = (l15 >> 1) & 3;
    const int khalf = lane >> 4;
    uint32_t offk[2];
    offk[0] = (uint32_t)((khalf)     ^ swzr) << 4;
    offk[1] = (uint32_t)((2 + khalf) ^ swzr) << 4;

    const uint32_t gbuf = sb + (uint32_t)g * GRP_BYTES;
    const int r_in = lane >> 2;
    const int cp2  = (lane & 3) << 1;

    for (int seg = 0; seg < NSEG; ++seg) {
        const bool isOut = (seg == 8);
        const int  h0 = seg * 128;
        const int  NC = isOut ? (SK / 32) : (4 * (seg + 1));
        const int  NCg = NC >> 1;
        const __nv_bfloat16* Wh = isOut ? g_WO_hi : (g_W_hi + (size_t)h0 * SK);
        const __nv_bfloat16* Wl = isOut ? g_WO_lo : (g_W_lo + (size_t)h0 * SK);

        float acc[2][4][4];
        #pragma unroll
        for (int a = 0; a < 2; ++a)
            #pragma unroll
            for (int b = 0; b < 4; ++b)
                #pragma unroll
                for (int c = 0; c < 4; ++c) acc[a][b][c] = 0.f;

        // prime pipeline: chunk g into buffer 0
        stage_chunk(gbuf, Sh, Sl, Wh, Wl, (g) * 32, gt);
        CP_COMMIT();

        for (int ci = 0; ci < NCg; ++ci) {
            if (ci + 1 < NCg) {
                stage_chunk(gbuf + (uint32_t)((ci + 1) & 1) * CH_BYTES,
                            Sh, Sl, Wh, Wl, (g + 2 * (ci + 1)) * 32, gt);
                CP_COMMIT();
                CP_WAIT(1);
            } else {
                CP_WAIT(0);
            }
            BAR_G(1 + g);

            const uint32_t bufb = gbuf + (uint32_t)(ci & 1) * CH_BYTES;
            const uint32_t aHi = bufb + CH_A_HI + rowA;
            const uint32_t aLo = bufb + CH_A_LO + rowA;
            const uint32_t bHi = bufb + CH_B_HI + rowB;
            const uint32_t bLo = bufb + CH_B_LO + rowB;

            #pragma unroll
            for (int ks = 0; ks < 2; ++ks) {
                const uint32_t ok = offk[ks];
                uint32_t ah0[4], ah1[4], al0[4], al1[4];
                uint32_t bh0[4], bh1[4], bl0[4], bl1[4];
                ldmx4(ah0, aHi + ok);        ldmx4(ah1, aHi + 1024 + ok);
                ldmx4(al0, aLo + ok);        ldmx4(al1, aLo + 1024 + ok);
                ldmx4(bh0, bHi + ok);        ldmx4(bh1, bHi + 1024 + ok);
                ldmx4(bl0, bLo + ok);        ldmx4(bl1, bLo + 1024 + ok);
                // hi*hi
                mma16816(acc[0][0], ah0, bh0[0], bh0[2]);
                mma16816(acc[0][1], ah0, bh0[1], bh0[3]);
                mma16816(acc[0][2], ah0, bh1[0], bh1[2]);
                mma16816(acc[0][3], ah0, bh1[1], bh1[3]);
                mma16816(acc[1][0], ah1, bh0[0], bh0[2]);
                mma16816(acc[1][1], ah1, bh0[1], bh0[3]);
                mma16816(acc[1][2], ah1, bh1[0], bh1[2]);
                mma16816(acc[1][3], ah1, bh1[1], bh1[3]);
                // hi*lo
                mma16816(acc[0][0], ah0, bl0[0], bl0[2]);
                mma16816(acc[0][1], ah0, bl0[1], bl0[3]);
                mma16816(acc[0][2], ah0, bl1[0], bl1[2]);
                mma16816(acc[0][3], ah0, bl1[1], bl1[3]);
                mma16816(acc[1][0], ah1, bl0[0], bl0[2]);
                mma16816(acc[1][1], ah1, bl0[1], bl0[3]);
                mma16816(acc[1][2], ah1, bl1[0], bl1[2]);
                mma16816(acc[1][3], ah1, bl1[1], bl1[3]);
                // lo*hi
                mma16816(acc[0][0], al0, bh0[0], bh0[2]);
                mma16816(acc[0][1], al0, bh0[1], bh0[3]);
                mma16816(acc[0][2], al0, bh1[0], bh1[2]);
                mma16816(acc[0][3], al0, bh1[1], bh1[3]);
                mma16816(acc[1][0], al1, bh0[0], bh0[2]);
                mma16816(acc[1][1], al1, bh0[1], bh0[3]);
                mma16816(acc[1][2], al1, bh1[0], bh1[2]);
                mma16816(acc[1][3], al1, bh1[1], bh1[3]);
            }
            BAR_G(1 + g);
        }
        __syncthreads();    // both groups' MMAs done; buffers free

        // ---- write partial acc to trans_g (overlays own buffers)
        {
            float* tr = (float*)(smem + g * GRP_BYTES);
            #pragma unroll
            for (int mi = 0; mi < 2; ++mi)
                #pragma unroll
                for (int nf = 0; nf < 4; ++nf) {
                    const int rowb = 32 * wr + 16 * mi + r_in;
                    const int colb = 32 * wc + 8 * nf + cp2;
                    tr[(colb    ) * TP + rowb    ] = acc[mi][nf][0];
                    tr[(colb + 1) * TP + rowb    ] = acc[mi][nf][1];
                    tr[(colb    ) * TP + rowb + 8] = acc[mi][nf][2];
                    tr[(colb + 1) * TP + rowb + 8] = acc[mi][nf][3];
                }
        }
        __syncthreads();

        const float* tr0 = (const float*)(smem);
        const float* tr1 = (const float*)(smem + GRP_BYTES);

        if (isOut) {
            // combine partials and store y
            const int row = tid >> 3;
            const int cb  = (tid & 7) * 16;
            float* od = out + (size_t)(row0 + row) * OUTD + cb;
            #pragma unroll
            for (int j = 0; j < 4; ++j) {
                float4 v;
                v.x = tr0[(cb + 4*j + 0) * TP + row] + tr1[(cb + 4*j + 0) * TP + row];
                v.y = tr0[(cb + 4*j + 1) * TP + row] + tr1[(cb + 4*j + 1) * TP + row];
                v.z = tr0[(cb + 4*j + 2) * TP + row] + tr1[(cb + 4*j + 2) * TP + row];
                v.w = tr0[(cb + 4*j + 3) * TP + row] + tr1[(cb + 4*j + 3) * TP + row];
                *(float4*)(od + 4*j) = v;
            }
        } else {
            // ---- stage fp32 diag: diagf[i*DP + c] = Bs[h0+c][h0+i]
            {
                const int c  = tid >> 2;
                const int i0 = (tid & 3) << 5;
                const float4* sp = (const float4*)(Bs + (size_t)(h0 + c) * HID + h0 + i0);
                #pragma unroll
                for (int k = 0; k < 8; ++k) {
                    float4 v = sp[k];
                    const int i = i0 + 4 * k;
                    diagf[(i + 0) * DP + c] = v.x;
                    diagf[(i + 1) * DP + c] = v.y;
                    diagf[(i + 2) * DP + c] = v.z;
                    diagf[(i + 3) * DP + c] = v.w;
                }
            }
            // ---- load sweep acc (sum of partials): warp rows 4wid..+3, lane cols 4lane..+3
            ull a2[4][2];
            #pragma unroll
            for (int q = 0; q < 4; ++q) {
                const int cc = 4 * lane + q;
                const float* p0 = tr0 + cc * TP + 4 * wid;
                const float* p1 = tr1 + cc * TP + 4 * wid;
                a2[q][0] = pack2(p0[0] + p1[0], p0[1] + p1[1]);
                a2[q][1] = pack2(p0[2] + p1[2], p0[3] + p1[3]);
            }
            __syncthreads();   // trans consumed, diag staged

            // ---- 128-step sequential sweep (shfl-only exchange)
            const int grow = row0 + 4 * wid + (lane & 3);
            __nv_bfloat16* ghi = g_S_hi + (size_t)grow * SK + IND + h0;
            __nv_bfloat16* glo = g_S_lo + (size_t)grow * SK + IND + h0;
            const int cbase = 4 * lane;

            #pragma unroll 4
            for (int ib = 0; ib < 32; ++ib) {
                #pragma unroll
                for (int q = 0; q < 4; ++q) {
                    const int i = 4 * ib + q;
                    ull g0 = __shfl_sync(0xffffffffu, a2[q][0], ib);
                    ull g1 = __shfl_sync(0xffffffffu, a2[q][1], ib);
                    float2 pp = unpack2((lane & 2) ? g1 : g0);
                    float v = (lane & 1) ? pp.y : pp.x;
                    float t = fast_tanh(v);
                    if (lane < 4) {
                        __nv_bfloat16 hb = __float2bfloat16_rn(t);
                        ghi[i] = hb;
                        glo[i] = __float2bfloat16_rn(t - __bfloat162float(hb));
                    }
                    float t0 = __shfl_sync(0xffffffffu, t, 0);
                    float t1 = __shfl_sync(0xffffffffu, t, 1);
                    float t2 = __shfl_sync(0xffffffffu, t, 2);
                    float t3 = __shfl_sync(0xffffffffu, t, 3);
                    ull s01 = pack2(t0, t1), s23 = pack2(t2, t3);
                    float4 b = *(const float4*)(diagf + i * DP + cbase);
                    if (cbase + 0 > i) { ull bb = dup2(b.x);
                        a2[0][0] = ffma2(s01, bb, a2[0][0]); a2[0][1] = ffma2(s23, bb, a2[0][1]); }
                    if (cbase + 1 > i) { ull bb = dup2(b.y);
                        a2[1][0] = ffma2(s01, bb, a2[1][0]); a2[1][1] = ffma2(s23, bb, a2[1][1]); }
                    if (cbase + 2 > i) { ull bb = dup2(b.z);
                        a2[2][0] = ffma2(s01, bb, a2[2][0]); a2[2][1] = ffma2(s23, bb, a2[2][1]); }
                    if (cbase + 3 > i) { ull bb = dup2(b.w);
                        a2[3][0] = ffma2(s01, bb, a2[3][0]); a2[3][1] = ffma2(s23, bb, a2[3][1]); }
                }
            }
            __syncthreads();   // s stores visible to both groups' staging
        }
    }
}

extern "C" void kernel_launch(void* const* d_in, const int* in_sizes, int n_in,
                              void* d_out, int out_size)
{
    const float* u  = (const float*)d_in[0];  // [8192,128]
    const float* Bw = (const float*)d_in[1];  // [1024,128]
    const float* Bs = (const float*)d_in[2];  // [1024,1024]
    const float* Ds = (const float*)d_in[3];  // [128,1024]
    const float* Dw = (const float*)d_in[4];  // [128,128]

    const int NTOT = T1 + T2 + T3;
    split_kernel<<<(NTOT + 255) / 256, 256>>>(u, Bw, Bs, Ds, Dw);

    cudaFuncSetAttribute(ren_main, cudaFuncAttributeMaxDynamicSharedMemorySize, SMEM_TOTAL);
    ren_main<<<BATCH / MB, THREADS, SMEM_TOTAL>>>(Bs, (float*)d_out);
}

// round 8
// speedup vs baseline: 2.4251x; 1.0281x over previous
#include <cuda_runtime.h>
#include <cuda_bf16.h>
#include <cstdint>

#define BATCH 8192
#define IND   128
#define HID   1024
#define OUTD  128
#define SK    1152           // S cols: [u(128) | s(1024)]
#define MB    32             // batch rows per CTA -> 256 CTAs (2 per SM)
#define THREADS 256
#define NSEG  9

// per-chunk buffer (20480 B): A 32x64B hi/lo, B 128x64B hi/lo (swizzled)
#define CH_A_HI 0
#define CH_A_LO 2048
#define CH_B_HI 4096
#define CH_B_LO 12288
#define CH_BYTES 20480       // x4 buffers = 81920
#define TRANS_OFF 81920
#define TP 37                // trans pitch (floats), 128 cols x 37
#define SMEM_TOTAL (81920 + 128*TP*4)   // 100864 -> 2 CTAs/SM

typedef unsigned long long ull;

__device__ __align__(256) __nv_bfloat16 g_S_hi[(size_t)BATCH * SK];
__device__ __align__(256) __nv_bfloat16 g_S_lo[(size_t)BATCH * SK];
__device__ __align__(256) __nv_bfloat16 g_W_hi[(size_t)HID * SK];
__device__ __align__(256) __nv_bfloat16 g_W_lo[(size_t)HID * SK];
__device__ __align__(256) __nv_bfloat16 g_WO_hi[(size_t)OUTD * SK];
__device__ __align__(256) __nv_bfloat16 g_WO_lo[(size_t)OUTD * SK];
__device__ __align__(256) float         g_diagT[8 * 128 * 128];   // [seg][i][c]

__device__ __forceinline__ uint32_t smem_u32(const void* p) {
    uint32_t a;
    asm("{ .reg .u64 t; cvta.to.shared.u64 t, %1; cvt.u32.u64 %0, t; }" : "=r"(a) : "l"(p));
    return a;
}
__device__ __forceinline__ ull ffma2(ull a, ull b, ull c) {
    ull d; asm("fma.rn.f32x2 %0, %1, %2, %3;" : "=l"(d) : "l"(a), "l"(b), "l"(c)); return d;
}
__device__ __forceinline__ ull dup2(float x) {
    ull d; asm("mov.b64 %0, {%1, %1};" : "=l"(d) : "f"(x)); return d;
}
__device__ __forceinline__ ull pack2(float x, float y) {
    ull d; asm("mov.b64 %0, {%1, %2};" : "=l"(d) : "f"(x), "f"(y)); return d;
}
__device__ __forceinline__ float2 unpack2(ull v) {
    float2 f; asm("mov.b64 {%0, %1}, %2;" : "=f"(f.x), "=f"(f.y) : "l"(v)); return f;
}
__device__ __forceinline__ float fast_tanh(float x) {
    float e; asm("ex2.approx.f32 %0, %1;" : "=f"(e) : "f"(x * 2.8853900817779268f));
    float r; asm("rcp.approx.f32 %0, %1;" : "=f"(r) : "f"(e + 1.0f));
    return fmaf(-2.0f, r, 1.0f);
}
__device__ __forceinline__ void ldmx4(uint32_t r[4], uint32_t a) {
    asm volatile("ldmatrix.sync.aligned.m8n8.x4.shared.b16 {%0,%1,%2,%3}, [%4];"
        : "=r"(r[0]), "=r"(r[1]), "=r"(r[2]), "=r"(r[3]) : "r"(a));
}
__device__ __forceinline__ void mma16816(float c[4], const uint32_t a[4],
                                         uint32_t b0, uint32_t b1) {
    asm volatile("mma.sync.aligned.m16n8k16.row.col.f32.bf16.bf16.f32 "
        "{%0,%1,%2,%3}, {%4,%5,%6,%7}, {%8,%9}, {%0,%1,%2,%3};"
        : "+f"(c[0]), "+f"(c[1]), "+f"(c[2]), "+f"(c[3])
        : "r"(a[0]), "r"(a[1]), "r"(a[2]), "r"(a[3]), "r"(b0), "r"(b1));
}
__device__ __forceinline__ void cp16(uint32_t dst, const void* src) {
    asm volatile("cp.async.cg.shared.global [%0], [%1], 16;" :: "r"(dst), "l"(src));
}
#define CP_COMMIT() asm volatile("cp.async.commit_group;" ::: "memory")
#define CP_WAIT(n)  asm volatile("cp.async.wait_group %0;" :: "n"(n) : "memory")

// ======== prologue: split inputs into bf16 hi+lo, transpose diag blocks ========
#define T1 (BATCH * IND)
#define T2 (HID * SK)
#define T3 (OUTD * SK)
#define T4 (8 * 128 * 128)

__device__ __forceinline__ void store_split(__nv_bfloat16* hi, __nv_bfloat16* lo,
                                            size_t idx, float v) {
    __nv_bfloat16 h = __float2bfloat16_rn(v);
    hi[idx] = h;
    lo[idx] = __float2bfloat16_rn(v - __bfloat162float(h));
}

__global__ void split_kernel(const float* __restrict__ u,  const float* __restrict__ Bw,
                             const float* __restrict__ Bs, const float* __restrict__ Ds,
                             const float* __restrict__ Dw) {
    int idx = blockIdx.x * blockDim.x + threadIdx.x;
    if (idx < T1) {
        int r = idx >> 7, k = idx & 127;
        store_split(g_S_hi, g_S_lo, (size_t)r * SK + k, u[idx]);
    } else if (idx < T1 + T2) {
        int i = idx - T1;
        int n = i / SK, k = i % SK;
        float v = (k < IND) ? Bw[n * IND + k] : Bs[(size_t)n * HID + (k - IND)];
        store_split(g_W_hi, g_W_lo, i, v);
    } else if (idx < T1 + T2 + T3) {
        int i = idx - T1 - T2;
        int n = i / SK, k = i % SK;
        float v = (k < IND) ? Dw[n * IND + k] : Ds[(size_t)n * HID + (k - IND)];
        store_split(g_WO_hi, g_WO_lo, i, v);
    } else if (idx < T1 + T2 + T3 + T4) {
        int i4 = idx - T1 - T2 - T3;
        int seg = i4 >> 14;
        int r   = (i4 >> 7) & 127;   // i within diag block
        int c   = i4 & 127;
        g_diagT[i4] = Bs[(size_t)(seg * 128 + c) * HID + seg * 128 + r];
    }
}

// stage one K=32 chunk: A 32 rows, B 128 rows, hi+lo, swizzled 64B rows
__device__ __forceinline__ void stage_chunk(uint32_t bufb,
        const __nv_bfloat16* __restrict__ Sh, const __nv_bfloat16* __restrict__ Sl,
        const __nv_bfloat16* __restrict__ Wh, const __nv_bfloat16* __restrict__ Wl,
        int kcol, int tid)
{
    if (tid < 128) {   // A: 128 pieces per buf
        const int row = tid >> 2, c16 = tid & 3;
        const uint32_t d = (uint32_t)row * 64 + 16u * (uint32_t)(c16 ^ ((row >> 1) & 3));
        const size_t so = (size_t)row * SK + kcol + c16 * 8;
        cp16(bufb + CH_A_HI + d, Sh + so);
        cp16(bufb + CH_A_LO + d, Sl + so);
    }
    #pragma unroll
    for (int h = 0; h < 2; ++h) {   // B: 512 pieces per buf -> 2/thread
        const int p = tid + h * 256;
        const int row = p >> 2, c16 = p & 3;
        const uint32_t d = (uint32_t)row * 64 + 16u * (uint32_t)(c16 ^ ((row >> 1) & 3));
        const size_t so = (size_t)row * SK + kcol + c16 * 8;
        cp16(bufb + CH_B_HI + d, Wh + so);
        cp16(bufb + CH_B_LO + d, Wl + so);
    }
}

// ======== main fused kernel (2 CTAs/SM) ========
__global__ void __launch_bounds__(THREADS, 2)
ren_main(float* __restrict__ out)
{
    extern __shared__ char smem[];
    const uint32_t sb = smem_u32(smem);
    float* trans = (float*)(smem + TRANS_OFF);

    const int tid  = threadIdx.x;
    const int wid  = tid >> 5;       // 0..7
    const int lane = tid & 31;
    const int wr   = wid & 1;        // 16-row strip
    const int wc   = wid >> 1;       // 32-col strip
    const int row0 = blockIdx.x * MB;

    const __nv_bfloat16* Sh = g_S_hi + (size_t)row0 * SK;
    const __nv_bfloat16* Sl = g_S_lo + (size_t)row0 * SK;

    // ldmatrix lane addressing (swizzled 64B rows)
    const int l15  = lane & 15;
    const uint32_t rowA = (uint32_t)(16 * wr + l15) * 64;
    const uint32_t rowB = (uint32_t)(32 * wc + l15) * 64;
    const int swzr  = (l15 >> 1) & 3;
    const int khalf = lane >> 4;
    uint32_t offk[2];
    offk[0] = (uint32_t)((khalf)     ^ swzr) << 4;
    offk[1] = (uint32_t)((2 + khalf) ^ swzr) << 4;

    const int r_in = lane >> 2;
    const int cp2  = (lane & 3) << 1;
    const int cbase = 4 * lane;

    // prime segment 0 (chunks 0,1 -> buffers 0,1)
    stage_chunk(sb,            Sh, Sl, g_W_hi, g_W_lo,  0, tid); CP_COMMIT();
    stage_chunk(sb + CH_BYTES, Sh, Sl, g_W_hi, g_W_lo, 32, tid); CP_COMMIT();

    for (int seg = 0; seg < NSEG; ++seg) {
        const bool isOut = (seg == 8);
        const int  NC = isOut ? (SK / 32) : (4 * (seg + 1));
        const __nv_bfloat16* Wh = isOut ? g_WO_hi : (g_W_hi + (size_t)seg * 128 * SK);
        const __nv_bfloat16* Wl = isOut ? g_WO_lo : (g_W_lo + (size_t)seg * 128 * SK);

        float acc[4][4];
        #pragma unroll
        for (int a = 0; a < 4; ++a)
            #pragma unroll
            for (int c = 0; c < 4; ++c) acc[a][c] = 0.f;

        for (int ci = 0; ci < NC; ++ci) {
            if (ci + 2 < NC) {
                stage_chunk(sb + (uint32_t)((ci + 2) & 3) * CH_BYTES,
                            Sh, Sl, Wh, Wl, (ci + 2) * 32, tid);
                CP_COMMIT();
                CP_WAIT(2);
            } else if (ci + 1 < NC) {
                CP_WAIT(1);
            } else {
                CP_WAIT(0);
            }
            __syncthreads();

            const uint32_t bufb = sb + (uint32_t)(ci & 3) * CH_BYTES;
            const uint32_t aHi = bufb + CH_A_HI + rowA;
            const uint32_t aLo = bufb + CH_A_LO + rowA;
            const uint32_t bHi = bufb + CH_B_HI + rowB;
            const uint32_t bLo = bufb + CH_B_LO + rowB;

            #pragma unroll
            for (int ks = 0; ks < 2; ++ks) {
                const uint32_t ok = offk[ks];
                uint32_t aH[4], aL[4], bh0[4], bh1[4], bl0[4], bl1[4];
                ldmx4(aH,  aHi + ok);
                ldmx4(aL,  aLo + ok);
                ldmx4(bh0, bHi + ok);        ldmx4(bh1, bHi + 1024 + ok);
                ldmx4(bl0, bLo + ok);        ldmx4(bl1, bLo + 1024 + ok);
                // hi*hi
                mma16816(acc[0], aH, bh0[0], bh0[2]);
                mma16816(acc[1], aH, bh0[1], bh0[3]);
                mma16816(acc[2], aH, bh1[0], bh1[2]);
                mma16816(acc[3], aH, bh1[1], bh1[3]);
                // hi*lo
                mma16816(acc[0], aH, bl0[0], bl0[2]);
                mma16816(acc[1], aH, bl0[1], bl0[3]);
                mma16816(acc[2], aH, bl1[0], bl1[2]);
                mma16816(acc[3], aH, bl1[1], bl1[3]);
                // lo*hi
                mma16816(acc[0], aL, bh0[0], bh0[2]);
                mma16816(acc[1], aL, bh0[1], bh0[3]);
                mma16816(acc[2], aL, bh1[0], bh1[2]);
                mma16816(acc[3], aL, bh1[1], bh1[3]);
            }
        }

        if (isOut) {
            // direct store from fragments
            #pragma unroll
            for (int nf = 0; nf < 4; ++nf) {
                const int row = 16 * wr + r_in;
                const int col = 32 * wc + 8 * nf + cp2;
                *(float2*)(out + (size_t)(row0 + row) * OUTD + col) =
                    make_float2(acc[nf][0], acc[nf][1]);
                *(float2*)(out + (size_t)(row0 + row + 8) * OUTD + col) =
                    make_float2(acc[nf][2], acc[nf][3]);
            }
        } else {
            // ---- transpose fragments into trans[col*TP + row]
            #pragma unroll
            for (int nf = 0; nf < 4; ++nf) {
                const int rowb = 16 * wr + r_in;
                const int colb = 32 * wc + 8 * nf + cp2;
                trans[(colb    ) * TP + rowb    ] = acc[nf][0];
                trans[(colb + 1) * TP + rowb    ] = acc[nf][1];
                trans[(colb    ) * TP + rowb + 8] = acc[nf][2];
                trans[(colb + 1) * TP + rowb + 8] = acc[nf][3];
            }
            __syncthreads();

            // ---- load sweep acc: warp rows 4wid..+3, lane cols 4lane..+3
            ull a2[4][2];
            #pragma unroll
            for (int q = 0; q < 4; ++q) {
                const float* tp = trans + (4 * lane + q) * TP + 4 * wid;
                a2[q][0] = pack2(tp[0], tp[1]);
                a2[q][1] = pack2(tp[2], tp[3]);
            }

            // ---- prime next segment (chunks 0,1 = u-region cols, sweep-independent)
            {
                const bool nOut = (seg + 1 == 8);
                const __nv_bfloat16* nWh = nOut ? g_WO_hi : (g_W_hi + (size_t)(seg + 1) * 128 * SK);
                const __nv_bfloat16* nWl = nOut ? g_WO_lo : (g_W_lo + (size_t)(seg + 1) * 128 * SK);
                stage_chunk(sb,            Sh, Sl, nWh, nWl,  0, tid); CP_COMMIT();
                stage_chunk(sb + CH_BYTES, Sh, Sl, nWh, nWl, 32, tid); CP_COMMIT();
            }

            // ---- 128-step sequential sweep; b prefetched from L2-resident g_diagT
            const int grow = row0 + 4 * wid + (lane & 3);
            __nv_bfloat16* ghi = g_S_hi + (size_t)grow * SK + IND + seg * 128;
            __nv_bfloat16* glo = g_S_lo + (size_t)grow * SK + IND + seg * 128;
            const float* dT = g_diagT + seg * 16384;

            float4 bn[4], bc[4];
            #pragma unroll
            for (int k = 0; k < 4; ++k)
                bn[k] = *(const float4*)(dT + k * 128 + cbase);

            for (int ib = 0; ib < 32; ++ib) {
                #pragma unroll
                for (int k = 0; k < 4; ++k) bc[k] = bn[k];
                if (ib < 31) {
                    #pragma unroll
                    for (int k = 0; k < 4; ++k)
                        bn[k] = *(const float4*)(dT + (4 * (ib + 1) + k) * 128 + cbase);
                }
                #pragma unroll
                for (int q = 0; q < 4; ++q) {
                    const int i = 4 * ib + q;
                    ull g0 = __shfl_sync(0xffffffffu, a2[q][0], ib);
                    ull g1 = __shfl_sync(0xffffffffu, a2[q][1], ib);
                    float2 pp = unpack2((lane & 2) ? g1 : g0);
                    float v = (lane & 1) ? pp.y : pp.x;
                    float t = fast_tanh(v);
                    if (lane < 4) {
                        __nv_bfloat16 hb = __float2bfloat16_rn(t);
                        ghi[i] = hb;
                        glo[i] = __float2bfloat16_rn(t - __bfloat162float(hb));
                    }
                    float t0 = __shfl_sync(0xffffffffu, t, 0);
                    float t1 = __shfl_sync(0xffffffffu, t, 1);
                    float t2 = __shfl_sync(0xffffffffu, t, 2);
                    float t3 = __shfl_sync(0xffffffffu, t, 3);
                    ull s01 = pack2(t0, t1), s23 = pack2(t2, t3);
                    const float4 b = bc[q];
                    if (cbase + 0 > i) { ull bb = dup2(b.x);
                        a2[0][0] = ffma2(s01, bb, a2[0][0]); a2[0][1] = ffma2(s23, bb, a2[0][1]); }
                    if (cbase + 1 > i) { ull bb = dup2(b.y);
                        a2[1][0] = ffma2(s01, bb, a2[1][0]); a2[1][1] = ffma2(s23, bb, a2[1][1]); }
                    if (cbase + 2 > i) { ull bb = dup2(b.z);
                        a2[2][0] = ffma2(s01, bb, a2[2][0]); a2[2][1] = ffma2(s23, bb, a2[2][1]); }
                    if (cbase + 3 > i) { ull bb = dup2(b.w);
                        a2[3][0] = ffma2(s01, bb, a2[3][0]); a2[3][1] = ffma2(s23, bb, a2[3][1]); }
                }
            }
            __syncthreads();   // s stores visible; trans free for next segment
        }
    }
}

extern "C" void kernel_launch(void* const* d_in, const int* in_sizes, int n_in,
                              void* d_out, int out_size)
{
    const float* u  = (const float*)d_in[0];  // [8192,128]
    const float* Bw = (const float*)d_in[1];  // [1024,128]
    const float* Bs = (const float*)d_in[2];  // [1024,1024]
    const float* Ds = (const float*)d_in[3];  // [128,1024]
    const float* Dw = (const float*)d_in[4];  // [128,128]

    const int NTOT = T1 + T2 + T3 + T4;
    split_kernel<<<(NTOT + 255) / 256, 256>>>(u, Bw, Bs, Ds, Dw);

    cudaFuncSetAttribute(ren_main, cudaFuncAttributeMaxDynamicSharedMemorySize, SMEM_TOTAL);
    ren_main<<<BATCH / MB, THREADS, SMEM_TOTAL>>>((float*)d_out);
}